// round 2
// baseline (speedup 1.0000x reference)
#include <cuda_runtime.h>

// Problem constants (fixed by the dataset)
#define N_ATOMS 50000
#define N_PAIRS 800000
#define FDIM    128
#define F3      384

// ---------------- scratch (device globals; no runtime allocation) ----------
__device__ int   g_count [N_ATOMS];
__device__ int   g_cursor[N_ATOMS];
__device__ int   g_offset[N_ATOMS + 1];
__device__ int   g_pairidx[N_PAIRS];
__device__ float g_h[(size_t)N_ATOMS * FDIM];   // 25.6 MB
__device__ float g_x[(size_t)N_ATOMS * F3];     // 76.8 MB

// ---------------- small float4 helpers -------------------------------------
__device__ __forceinline__ float4 f4add(float4 a, float4 b) {
    return make_float4(a.x + b.x, a.y + b.y, a.z + b.z, a.w + b.w);
}
__device__ __forceinline__ float4 f4mul(float4 a, float4 b) {
    return make_float4(a.x * b.x, a.y * b.y, a.z * b.z, a.w * b.w);
}
__device__ __forceinline__ float4 f4fma(float4 a, float4 b, float4 c) {
    return make_float4(fmaf(a.x, b.x, c.x), fmaf(a.y, b.y, c.y),
                       fmaf(a.z, b.z, c.z), fmaf(a.w, b.w, c.w));
}
__device__ __forceinline__ float4 f4fmas(float4 a, float s, float4 c) {
    return make_float4(fmaf(a.x, s, c.x), fmaf(a.y, s, c.y),
                       fmaf(a.z, s, c.z), fmaf(a.w, s, c.w));
}

// ---------------- CSR build -------------------------------------------------
__global__ void k_zero() {
    int i = blockIdx.x * blockDim.x + threadIdx.x;
    if (i < N_ATOMS) { g_count[i] = 0; g_cursor[i] = 0; }
}

__global__ void k_hist(const int* __restrict__ idx_i) {
    int p = blockIdx.x * blockDim.x + threadIdx.x;
    if (p < N_PAIRS) atomicAdd(&g_count[idx_i[p]], 1);
}

// single-block exclusive scan over g_count -> g_offset
__global__ void k_scan() {
    __shared__ int sh[1024];
    int running = 0;
    for (int base = 0; base < N_ATOMS; base += 1024) {
        int idx = base + (int)threadIdx.x;
        int v = (idx < N_ATOMS) ? g_count[idx] : 0;
        sh[threadIdx.x] = v;
        __syncthreads();
        #pragma unroll
        for (int off = 1; off < 1024; off <<= 1) {
            int t = (threadIdx.x >= (unsigned)off) ? sh[threadIdx.x - off] : 0;
            __syncthreads();
            sh[threadIdx.x] += t;
            __syncthreads();
        }
        if (idx < N_ATOMS) g_offset[idx] = running + sh[threadIdx.x] - v;
        running += sh[1023];
        __syncthreads();
    }
    if (threadIdx.x == 0) g_offset[N_ATOMS] = running;
}

__global__ void k_scatter(const int* __restrict__ idx_i) {
    int p = blockIdx.x * blockDim.x + threadIdx.x;
    if (p < N_PAIRS) {
        int i = idx_i[p];
        int pos = atomicAdd(&g_cursor[i], 1);
        g_pairidx[g_offset[i] + pos] = p;
    }
}

// ---------------- fp32 GEMM: out[m,n] = sum_k A[m,k]*W[n,k] + b[n] ----------
// BM=BN=64, BK=32, 256 threads, 4x4 microtile. K fixed at 128.
__global__ __launch_bounds__(256)
void gemm_kernel(const float* __restrict__ A, const float* __restrict__ W,
                 const float* __restrict__ bias, float* __restrict__ out,
                 int M, int N, int doSilu) {
    const int K = 128;
    const int BM = 64, BN = 64, BK = 32;
    __shared__ float As[BK][BM + 4];
    __shared__ float Ws[BK][BN + 4];

    int tid = threadIdx.x;
    int bm = blockIdx.y * BM, bn = blockIdx.x * BN;
    int tx = tid % 16, ty = tid / 16;
    int row0 = ty * 4, col0 = tx * 4;

    float acc[4][4];
    #pragma unroll
    for (int i = 0; i < 4; i++)
        #pragma unroll
        for (int j = 0; j < 4; j++) acc[i][j] = 0.f;

    for (int k0 = 0; k0 < K; k0 += BK) {
        #pragma unroll
        for (int r = 0; r < 2; ++r) {
            int t  = tid + r * 256;
            int ml = t >> 3;            // 0..63
            int kq = (t & 7) * 4;       // 0..28
            float4 v = make_float4(0, 0, 0, 0);
            int m = bm + ml;
            if (m < M)
                v = *reinterpret_cast<const float4*>(A + (size_t)m * K + k0 + kq);
            As[kq + 0][ml] = v.x; As[kq + 1][ml] = v.y;
            As[kq + 2][ml] = v.z; As[kq + 3][ml] = v.w;

            float4 wv = *reinterpret_cast<const float4*>(W + (size_t)(bn + ml) * K + k0 + kq);
            Ws[kq + 0][ml] = wv.x; Ws[kq + 1][ml] = wv.y;
            Ws[kq + 2][ml] = wv.z; Ws[kq + 3][ml] = wv.w;
        }
        __syncthreads();

        #pragma unroll
        for (int kk = 0; kk < BK; ++kk) {
            float4 a = *reinterpret_cast<const float4*>(&As[kk][row0]);
            float4 b = *reinterpret_cast<const float4*>(&Ws[kk][col0]);
            float av[4] = {a.x, a.y, a.z, a.w};
            float bv[4] = {b.x, b.y, b.z, b.w};
            #pragma unroll
            for (int i = 0; i < 4; i++)
                #pragma unroll
                for (int j = 0; j < 4; j++)
                    acc[i][j] = fmaf(av[i], bv[j], acc[i][j]);
        }
        __syncthreads();
    }

    #pragma unroll
    for (int i = 0; i < 4; i++) {
        int m = bm + row0 + i;
        if (m >= M) continue;
        #pragma unroll
        for (int j = 0; j < 4; j++) {
            int n = bn + col0 + j;
            float v = acc[i][j] + bias[n];
            if (doSilu) v = v / (1.0f + __expf(-v));
            out[(size_t)m * N + n] = v;
        }
    }
}

// ---------------- aggregation: one warp per atom, no float atomics ---------
__global__ __launch_bounds__(128)
void k_agg(const float* __restrict__ q, const float* __restrict__ mu,
           const float* __restrict__ Wij, const float* __restrict__ dir,
           const int* __restrict__ idxj, float* __restrict__ out) {
    int warp = threadIdx.x >> 5;
    int lane = threadIdx.x & 31;
    int i = blockIdx.x * 4 + warp;
    if (i >= N_ATOMS) return;

    int s = g_offset[i], e = g_offset[i + 1];

    float4 aq = make_float4(0, 0, 0, 0);
    float4 a0 = aq, a1 = aq, a2 = aq;

    int t = s;
    int p_next = 0, j_next = 0;
    if (t < e) { p_next = g_pairidx[t]; j_next = idxj[p_next]; }

    for (; t < e; ++t) {
        int p = p_next, j = j_next;
        if (t + 1 < e) { p_next = g_pairidx[t + 1]; j_next = idxj[p_next]; }

        const float4* wp = reinterpret_cast<const float4*>(Wij) + (size_t)p * 96;
        const float4* xp = reinterpret_cast<const float4*>(g_x) + (size_t)j * 96;
        const float4* mp = reinterpret_cast<const float4*>(mu)  + (size_t)j * 96;

        float4 w0 = wp[lane], w1 = wp[lane + 32], w2 = wp[lane + 64];
        float4 x0 = xp[lane], x1 = xp[lane + 32], x2 = xp[lane + 64];
        float4 m0 = mp[lane], m1 = mp[lane + 32], m2 = mp[lane + 64];

        float d0 = __ldg(dir + (size_t)p * 3 + 0);
        float d1 = __ldg(dir + (size_t)p * 3 + 1);
        float d2 = __ldg(dir + (size_t)p * 3 + 2);

        aq = f4fma(w0, x0, aq);                 // dq
        float4 R  = f4mul(w1, x1);              // dmuR
        float4 MM = f4mul(w2, x2);              // dmumu
        a0 = f4fma(MM, m0, f4fmas(R, d0, a0));
        a1 = f4fma(MM, m1, f4fmas(R, d1, a1));
        a2 = f4fma(MM, m2, f4fmas(R, d2, a2));
    }

    // outputs: q_out first [N,1,F], then mu_out [N,3,F]
    const float4* qp = reinterpret_cast<const float4*>(q) + (size_t)i * 32;
    float4* oq = reinterpret_cast<float4*>(out) + (size_t)i * 32;
    oq[lane] = f4add(qp[lane], aq);

    const float4* mup = reinterpret_cast<const float4*>(mu) + (size_t)i * 96;
    float4* om = reinterpret_cast<float4*>(out + (size_t)N_ATOMS * FDIM) + (size_t)i * 96;
    om[lane]      = f4add(mup[lane],      a0);
    om[lane + 32] = f4add(mup[lane + 32], a1);
    om[lane + 64] = f4add(mup[lane + 64], a2);
}

// ---------------- launch ----------------------------------------------------
extern "C" void kernel_launch(void* const* d_in, const int* in_sizes, int n_in,
                              void* d_out, int out_size) {
    const float* q   = (const float*)d_in[0];
    const float* mu  = (const float*)d_in[1];
    const float* Wij = (const float*)d_in[2];
    const float* dir = (const float*)d_in[3];
    const int*   pl  = (const int*)d_in[4];
    const float* W1  = (const float*)d_in[5];
    const float* b1  = (const float*)d_in[6];
    const float* W2  = (const float*)d_in[7];
    const float* b2  = (const float*)d_in[8];
    float* out = (float*)d_out;

    const int* idx_i = pl;
    const int* idx_j = pl + N_PAIRS;

    float *hbuf = nullptr, *xbuf = nullptr;
    cudaGetSymbolAddress((void**)&hbuf, g_h);
    cudaGetSymbolAddress((void**)&xbuf, g_x);

    // CSR build (integer atomics only)
    k_zero   <<<(N_ATOMS + 255) / 256, 256>>>();
    k_hist   <<<(N_PAIRS + 255) / 256, 256>>>(idx_i);
    k_scan   <<<1, 1024>>>();
    k_scatter<<<(N_PAIRS + 255) / 256, 256>>>(idx_i);

    // x = W2 . silu(W1 . q + b1) + b2
    dim3 g1(FDIM / 64, (N_ATOMS + 63) / 64);
    gemm_kernel<<<g1, 256>>>(q, W1, b1, hbuf, N_ATOMS, FDIM, 1);
    dim3 g2(F3 / 64, (N_ATOMS + 63) / 64);
    gemm_kernel<<<g2, 256>>>(hbuf, W2, b2, xbuf, N_ATOMS, F3, 0);

    // per-atom gather + epilogue
    k_agg<<<N_ATOMS / 4, 128>>>(q, mu, Wij, dir, idx_j, out);
}

// round 3
// speedup vs baseline: 1.1245x; 1.1245x over previous
#include <cuda_runtime.h>

#define N_ATOMS 50000
#define N_PAIRS 800000
#define FDIM    128
#define F3      384

// ---------------- scratch (device globals; no runtime allocation) ----------
__device__ int   g_count [N_ATOMS];
__device__ int   g_cursor[N_ATOMS];
__device__ int   g_offset[N_ATOMS + 1];
__device__ int   g_pairidx[N_PAIRS];
__device__ float g_h[(size_t)N_ATOMS * FDIM];   // 25.6 MB
__device__ float g_x[(size_t)N_ATOMS * F3];     // 76.8 MB

// ---------------- small float4 helpers -------------------------------------
__device__ __forceinline__ float4 f4add(float4 a, float4 b) {
    return make_float4(a.x + b.x, a.y + b.y, a.z + b.z, a.w + b.w);
}
__device__ __forceinline__ float4 f4mul(float4 a, float4 b) {
    return make_float4(a.x * b.x, a.y * b.y, a.z * b.z, a.w * b.w);
}
__device__ __forceinline__ float4 f4fma(float4 a, float4 b, float4 c) {
    return make_float4(fmaf(a.x, b.x, c.x), fmaf(a.y, b.y, c.y),
                       fmaf(a.z, b.z, c.z), fmaf(a.w, b.w, c.w));
}
__device__ __forceinline__ float4 f4fmas(float4 a, float s, float4 c) {
    return make_float4(fmaf(a.x, s, c.x), fmaf(a.y, s, c.y),
                       fmaf(a.z, s, c.z), fmaf(a.w, s, c.w));
}

// ---------------- CSR build -------------------------------------------------
__global__ void k_zero() {
    int i = blockIdx.x * blockDim.x + threadIdx.x;
    if (i < N_ATOMS) { g_count[i] = 0; g_cursor[i] = 0; }
}

__global__ void k_hist(const int* __restrict__ idx_i) {
    int p = blockIdx.x * blockDim.x + threadIdx.x;
    if (p < N_PAIRS) atomicAdd(&g_count[idx_i[p]], 1);
}

// single-block exclusive scan, warp-shuffle two-level (3 barriers/iteration)
__global__ void k_scan() {
    __shared__ int warpsum[33];
    int lane = threadIdx.x & 31, wid = threadIdx.x >> 5;
    int running = 0;
    for (int base = 0; base < N_ATOMS; base += 1024) {
        int idx = base + (int)threadIdx.x;
        int v = (idx < N_ATOMS) ? g_count[idx] : 0;
        int incl = v;
        #pragma unroll
        for (int off = 1; off < 32; off <<= 1) {
            int t = __shfl_up_sync(0xffffffff, incl, off);
            if (lane >= off) incl += t;
        }
        if (lane == 31) warpsum[wid] = incl;
        __syncthreads();
        if (wid == 0) {
            int s = warpsum[lane];
            int si = s;
            #pragma unroll
            for (int off = 1; off < 32; off <<= 1) {
                int t = __shfl_up_sync(0xffffffff, si, off);
                if (lane >= off) si += t;
            }
            warpsum[lane] = si - s;          // exclusive warp prefix
            if (lane == 31) warpsum[32] = si; // block total
        }
        __syncthreads();
        if (idx < N_ATOMS) g_offset[idx] = running + warpsum[wid] + incl - v;
        running += warpsum[32];
        __syncthreads();                      // protect warpsum for next iter
    }
    if (threadIdx.x == 0) g_offset[N_ATOMS] = running;
}

__global__ void k_scatter(const int* __restrict__ idx_i) {
    int p = blockIdx.x * blockDim.x + threadIdx.x;
    if (p < N_PAIRS) {
        int i = idx_i[p];
        int pos = atomicAdd(&g_cursor[i], 1);
        g_pairidx[g_offset[i] + pos] = p;
    }
}

// ---------------- 3xTF32 tensor-core GEMM ----------------------------------
// out[m,n] = sum_k A[m,k]*W[n,k] + b[n], K=128 fixed.
// Block 256 thr (8 warps, 4x2), BM=128, BN=64, BK=16, warp tile 32x32.
__device__ __forceinline__ unsigned cvt_tf32(float x) {
    unsigned r; asm("cvt.rna.tf32.f32 %0, %1;" : "=r"(r) : "f"(x)); return r;
}
__device__ __forceinline__ void mma_tf32(float* d, const unsigned* a, const unsigned* b) {
    asm volatile(
        "mma.sync.aligned.m16n8k8.row.col.f32.tf32.tf32.f32 "
        "{%0,%1,%2,%3}, {%4,%5,%6,%7}, {%8,%9}, {%0,%1,%2,%3};"
        : "+f"(d[0]), "+f"(d[1]), "+f"(d[2]), "+f"(d[3])
        : "r"(a[0]), "r"(a[1]), "r"(a[2]), "r"(a[3]), "r"(b[0]), "r"(b[1]));
}

#define GBM 128
#define GBN 64
#define GBK 16
#define SROW 20   // smem row stride in floats (conflict-free, 16B aligned)

__global__ __launch_bounds__(256)
void gemm_tc(const float* __restrict__ A, const float* __restrict__ W,
             const float* __restrict__ bias, float* __restrict__ out,
             int M, int N, int doSilu) {
    __shared__ float As[GBM * SROW];
    __shared__ float Ws[GBN * SROW];

    int tid  = threadIdx.x;
    int warp = tid >> 5, lane = tid & 31;
    int g = lane >> 2, t4 = lane & 3;
    int wm = warp >> 1, wn = warp & 1;           // 4 x 2 warp grid
    int bm = blockIdx.y * GBM, bn = blockIdx.x * GBN;

    float acc[2][4][4];
    #pragma unroll
    for (int i = 0; i < 2; i++)
        #pragma unroll
        for (int j = 0; j < 4; j++)
            #pragma unroll
            for (int k = 0; k < 4; k++) acc[i][j][k] = 0.f;

    for (int k0 = 0; k0 < 128; k0 += GBK) {
        // stage A tile (128x16): 512 float4, 2 per thread
        #pragma unroll
        for (int r = 0; r < 2; r++) {
            int t  = tid + r * 256;
            int ml = t >> 2, kq = (t & 3) * 4;
            int m = bm + ml;
            float4 v = make_float4(0, 0, 0, 0);
            if (m < M) v = *reinterpret_cast<const float4*>(A + (size_t)m * 128 + k0 + kq);
            *reinterpret_cast<float4*>(As + ml * SROW + kq) = v;
        }
        // stage W tile (64x16): 256 float4, 1 per thread
        {
            int nl = tid >> 2, kq = (tid & 3) * 4;
            float4 v = *reinterpret_cast<const float4*>(W + (size_t)(bn + nl) * 128 + k0 + kq);
            *reinterpret_cast<float4*>(Ws + nl * SROW + kq) = v;
        }
        __syncthreads();

        #pragma unroll
        for (int ks = 0; ks < 2; ks++) {
            int kb = ks * 8;
            unsigned ah[2][4], al[2][4], bh[4][2], bl[4][2];
            #pragma unroll
            for (int tm = 0; tm < 2; tm++) {
                int mb = wm * 32 + tm * 16;
                float f0 = As[(mb + g)     * SROW + kb + t4];
                float f1 = As[(mb + 8 + g) * SROW + kb + t4];
                float f2 = As[(mb + g)     * SROW + kb + t4 + 4];
                float f3 = As[(mb + 8 + g) * SROW + kb + t4 + 4];
                ah[tm][0] = cvt_tf32(f0); al[tm][0] = cvt_tf32(f0 - __uint_as_float(ah[tm][0]));
                ah[tm][1] = cvt_tf32(f1); al[tm][1] = cvt_tf32(f1 - __uint_as_float(ah[tm][1]));
                ah[tm][2] = cvt_tf32(f2); al[tm][2] = cvt_tf32(f2 - __uint_as_float(ah[tm][2]));
                ah[tm][3] = cvt_tf32(f3); al[tm][3] = cvt_tf32(f3 - __uint_as_float(ah[tm][3]));
            }
            #pragma unroll
            for (int tn = 0; tn < 4; tn++) {
                int nb = wn * 32 + tn * 8;
                float f0 = Ws[(nb + g) * SROW + kb + t4];
                float f1 = Ws[(nb + g) * SROW + kb + t4 + 4];
                bh[tn][0] = cvt_tf32(f0); bl[tn][0] = cvt_tf32(f0 - __uint_as_float(bh[tn][0]));
                bh[tn][1] = cvt_tf32(f1); bl[tn][1] = cvt_tf32(f1 - __uint_as_float(bh[tn][1]));
            }
            #pragma unroll
            for (int tm = 0; tm < 2; tm++)
                #pragma unroll
                for (int tn = 0; tn < 4; tn++) {
                    mma_tf32(acc[tm][tn], ah[tm], bh[tn]);
                    mma_tf32(acc[tm][tn], al[tm], bh[tn]);
                    mma_tf32(acc[tm][tn], ah[tm], bl[tn]);
                }
        }
        __syncthreads();
    }

    // epilogue: bias (+ optional silu), float2 stores
    #pragma unroll
    for (int tm = 0; tm < 2; tm++) {
        #pragma unroll
        for (int tn = 0; tn < 4; tn++) {
            int row0 = bm + wm * 32 + tm * 16 + g;
            int col  = bn + wn * 32 + tn * 8 + t4 * 2;
            float b0 = __ldg(bias + col), b1 = __ldg(bias + col + 1);
            float v0 = acc[tm][tn][0] + b0;
            float v1 = acc[tm][tn][1] + b1;
            float v2 = acc[tm][tn][2] + b0;
            float v3 = acc[tm][tn][3] + b1;
            if (doSilu) {
                v0 = v0 / (1.0f + __expf(-v0));
                v1 = v1 / (1.0f + __expf(-v1));
                v2 = v2 / (1.0f + __expf(-v2));
                v3 = v3 / (1.0f + __expf(-v3));
            }
            if (row0 < M)
                *reinterpret_cast<float2*>(out + (size_t)row0 * N + col) = make_float2(v0, v1);
            if (row0 + 8 < M)
                *reinterpret_cast<float2*>(out + (size_t)(row0 + 8) * N + col) = make_float2(v2, v3);
        }
    }
}

// ---------------- aggregation: one warp per atom, no float atomics ---------
__global__ __launch_bounds__(128)
void k_agg(const float* __restrict__ q, const float* __restrict__ mu,
           const float* __restrict__ Wij, const float* __restrict__ dir,
           const int* __restrict__ idxj, float* __restrict__ out) {
    int warp = threadIdx.x >> 5;
    int lane = threadIdx.x & 31;
    int i = blockIdx.x * 4 + warp;
    if (i >= N_ATOMS) return;

    int s = g_offset[i], e = g_offset[i + 1];

    float4 aq = make_float4(0, 0, 0, 0);
    float4 a0 = aq, a1 = aq, a2 = aq;

    int t = s;
    int p_next = 0, j_next = 0;
    if (t < e) { p_next = g_pairidx[t]; j_next = idxj[p_next]; }

    for (; t < e; ++t) {
        int p = p_next, j = j_next;
        if (t + 1 < e) { p_next = g_pairidx[t + 1]; j_next = idxj[p_next]; }

        const float4* wp = reinterpret_cast<const float4*>(Wij) + (size_t)p * 96;
        const float4* xp = reinterpret_cast<const float4*>(g_x) + (size_t)j * 96;
        const float4* mp = reinterpret_cast<const float4*>(mu)  + (size_t)j * 96;

        float4 w0 = wp[lane], w1 = wp[lane + 32], w2 = wp[lane + 64];
        float4 x0 = xp[lane], x1 = xp[lane + 32], x2 = xp[lane + 64];
        float4 m0 = mp[lane], m1 = mp[lane + 32], m2 = mp[lane + 64];

        float d0 = __ldg(dir + (size_t)p * 3 + 0);
        float d1 = __ldg(dir + (size_t)p * 3 + 1);
        float d2 = __ldg(dir + (size_t)p * 3 + 2);

        aq = f4fma(w0, x0, aq);                 // dq
        float4 R  = f4mul(w1, x1);              // dmuR
        float4 MM = f4mul(w2, x2);              // dmumu
        a0 = f4fma(MM, m0, f4fmas(R, d0, a0));
        a1 = f4fma(MM, m1, f4fmas(R, d1, a1));
        a2 = f4fma(MM, m2, f4fmas(R, d2, a2));
    }

    // outputs: q_out first [N,1,F], then mu_out [N,3,F]
    const float4* qp = reinterpret_cast<const float4*>(q) + (size_t)i * 32;
    float4* oq = reinterpret_cast<float4*>(out) + (size_t)i * 32;
    oq[lane] = f4add(qp[lane], aq);

    const float4* mup = reinterpret_cast<const float4*>(mu) + (size_t)i * 96;
    float4* om = reinterpret_cast<float4*>(out + (size_t)N_ATOMS * FDIM) + (size_t)i * 96;
    om[lane]      = f4add(mup[lane],      a0);
    om[lane + 32] = f4add(mup[lane + 32], a1);
    om[lane + 64] = f4add(mup[lane + 64], a2);
}

// ---------------- launch ----------------------------------------------------
extern "C" void kernel_launch(void* const* d_in, const int* in_sizes, int n_in,
                              void* d_out, int out_size) {
    const float* q   = (const float*)d_in[0];
    const float* mu  = (const float*)d_in[1];
    const float* Wij = (const float*)d_in[2];
    const float* dir = (const float*)d_in[3];
    const int*   pl  = (const int*)d_in[4];
    const float* W1  = (const float*)d_in[5];
    const float* b1  = (const float*)d_in[6];
    const float* W2  = (const float*)d_in[7];
    const float* b2  = (const float*)d_in[8];
    float* out = (float*)d_out;

    const int* idx_i = pl;
    const int* idx_j = pl + N_PAIRS;

    float *hbuf = nullptr, *xbuf = nullptr;
    cudaGetSymbolAddress((void**)&hbuf, g_h);
    cudaGetSymbolAddress((void**)&xbuf, g_x);

    // CSR build (integer atomics only)
    k_zero   <<<(N_ATOMS + 255) / 256, 256>>>();
    k_hist   <<<(N_PAIRS + 255) / 256, 256>>>(idx_i);
    k_scan   <<<1, 1024>>>();
    k_scatter<<<(N_PAIRS + 255) / 256, 256>>>(idx_i);

    // x = W2 . silu(W1 . q + b1) + b2   (3xTF32 tensor-core GEMMs)
    dim3 g1(FDIM / GBN, (N_ATOMS + GBM - 1) / GBM);
    gemm_tc<<<g1, 256>>>(q, W1, b1, hbuf, N_ATOMS, FDIM, 1);
    dim3 g2(F3 / GBN, (N_ATOMS + GBM - 1) / GBM);
    gemm_tc<<<g2, 256>>>(hbuf, W2, b2, xbuf, N_ATOMS, F3, 0);

    // per-atom gather + epilogue
    k_agg<<<N_ATOMS / 4, 128>>>(q, mu, Wij, dir, idx_j, out);
}

// round 4
// speedup vs baseline: 1.3082x; 1.1633x over previous
#include <cuda_runtime.h>
#include <cuda_fp16.h>

#define N_ATOMS 50000
#define N_PAIRS 800000
#define FDIM    128
#define F3      384

// ---------------- scratch (device globals; no runtime allocation) ----------
__device__ int    g_count [N_ATOMS];
__device__ int    g_cursor[N_ATOMS];
__device__ int    g_offset[N_ATOMS + 1];
__device__ int    g_pairidx[N_PAIRS];
__device__ float  g_h  [(size_t)N_ATOMS * FDIM];  // 25.6 MB
__device__ __half g_xh [(size_t)N_ATOMS * F3];    // 38.4 MB (x in fp16)
__device__ __half g_muh[(size_t)N_ATOMS * F3];    // 38.4 MB (mu in fp16)

// ---------------- small float4 helpers -------------------------------------
__device__ __forceinline__ float4 f4add(float4 a, float4 b) {
    return make_float4(a.x + b.x, a.y + b.y, a.z + b.z, a.w + b.w);
}
__device__ __forceinline__ float4 f4mul(float4 a, float4 b) {
    return make_float4(a.x * b.x, a.y * b.y, a.z * b.z, a.w * b.w);
}
__device__ __forceinline__ float4 f4fma(float4 a, float4 b, float4 c) {
    return make_float4(fmaf(a.x, b.x, c.x), fmaf(a.y, b.y, c.y),
                       fmaf(a.z, b.z, c.z), fmaf(a.w, b.w, c.w));
}
__device__ __forceinline__ float4 f4fmas(float4 a, float s, float4 c) {
    return make_float4(fmaf(a.x, s, c.x), fmaf(a.y, s, c.y),
                       fmaf(a.z, s, c.z), fmaf(a.w, s, c.w));
}
// 4 halves (as uint2) -> float4
__device__ __forceinline__ float4 h4tof4(uint2 u) {
    __half2 a = *reinterpret_cast<__half2*>(&u.x);
    __half2 b = *reinterpret_cast<__half2*>(&u.y);
    float2 fa = __half22float2(a), fb = __half22float2(b);
    return make_float4(fa.x, fa.y, fb.x, fb.y);
}

// ---------------- CSR build -------------------------------------------------
__global__ void k_zero() {
    int i = blockIdx.x * blockDim.x + threadIdx.x;
    if (i < N_ATOMS) { g_count[i] = 0; g_cursor[i] = 0; }
}

__global__ void k_hist(const int* __restrict__ idx_i) {
    int p = blockIdx.x * blockDim.x + threadIdx.x;
    if (p < N_PAIRS) atomicAdd(&g_count[idx_i[p]], 1);
}

// single-block exclusive scan, warp-shuffle two-level
__global__ void k_scan() {
    __shared__ int warpsum[33];
    int lane = threadIdx.x & 31, wid = threadIdx.x >> 5;
    int running = 0;
    for (int base = 0; base < N_ATOMS; base += 1024) {
        int idx = base + (int)threadIdx.x;
        int v = (idx < N_ATOMS) ? g_count[idx] : 0;
        int incl = v;
        #pragma unroll
        for (int off = 1; off < 32; off <<= 1) {
            int t = __shfl_up_sync(0xffffffff, incl, off);
            if (lane >= off) incl += t;
        }
        if (lane == 31) warpsum[wid] = incl;
        __syncthreads();
        if (wid == 0) {
            int s = warpsum[lane];
            int si = s;
            #pragma unroll
            for (int off = 1; off < 32; off <<= 1) {
                int t = __shfl_up_sync(0xffffffff, si, off);
                if (lane >= off) si += t;
            }
            warpsum[lane] = si - s;
            if (lane == 31) warpsum[32] = si;
        }
        __syncthreads();
        if (idx < N_ATOMS) g_offset[idx] = running + warpsum[wid] + incl - v;
        running += warpsum[32];
        __syncthreads();
    }
    if (threadIdx.x == 0) g_offset[N_ATOMS] = running;
}

__global__ void k_scatter(const int* __restrict__ idx_i) {
    int p = blockIdx.x * blockDim.x + threadIdx.x;
    if (p < N_PAIRS) {
        int i = idx_i[p];
        int pos = atomicAdd(&g_cursor[i], 1);
        g_pairidx[g_offset[i] + pos] = p;
    }
}

// ---------------- mu -> fp16 mirror ----------------------------------------
__global__ void k_cvt_mu(const float* __restrict__ mu) {
    size_t i = (size_t)blockIdx.x * blockDim.x + threadIdx.x;   // float4 index
    size_t n4 = (size_t)N_ATOMS * F3 / 4;
    if (i >= n4) return;
    float4 v = reinterpret_cast<const float4*>(mu)[i];
    __half2 h0 = __floats2half2_rn(v.x, v.y);
    __half2 h1 = __floats2half2_rn(v.z, v.w);
    uint2 u;
    u.x = *reinterpret_cast<unsigned*>(&h0);
    u.y = *reinterpret_cast<unsigned*>(&h1);
    reinterpret_cast<uint2*>(g_muh)[i] = u;
}

// ---------------- 3xTF32 tensor-core GEMM ----------------------------------
__device__ __forceinline__ unsigned cvt_tf32(float x) {
    unsigned r; asm("cvt.rna.tf32.f32 %0, %1;" : "=r"(r) : "f"(x)); return r;
}
__device__ __forceinline__ void mma_tf32(float* d, const unsigned* a, const unsigned* b) {
    asm volatile(
        "mma.sync.aligned.m16n8k8.row.col.f32.tf32.tf32.f32 "
        "{%0,%1,%2,%3}, {%4,%5,%6,%7}, {%8,%9}, {%0,%1,%2,%3};"
        : "+f"(d[0]), "+f"(d[1]), "+f"(d[2]), "+f"(d[3])
        : "r"(a[0]), "r"(a[1]), "r"(a[2]), "r"(a[3]), "r"(b[0]), "r"(b[1]));
}

#define GBM 128
#define GBN 64
#define GBK 16
#define SROW 20

template<bool OUT_HALF, bool DO_SILU>
__global__ __launch_bounds__(256)
void gemm_tc(const float* __restrict__ A, const float* __restrict__ W,
             const float* __restrict__ bias, void* __restrict__ outv,
             int M, int N) {
    __shared__ float As[GBM * SROW];
    __shared__ float Ws[GBN * SROW];

    int tid  = threadIdx.x;
    int warp = tid >> 5, lane = tid & 31;
    int g = lane >> 2, t4 = lane & 3;
    int wm = warp >> 1, wn = warp & 1;
    int bm = blockIdx.y * GBM, bn = blockIdx.x * GBN;

    float acc[2][4][4];
    #pragma unroll
    for (int i = 0; i < 2; i++)
        #pragma unroll
        for (int j = 0; j < 4; j++)
            #pragma unroll
            for (int k = 0; k < 4; k++) acc[i][j][k] = 0.f;

    for (int k0 = 0; k0 < 128; k0 += GBK) {
        #pragma unroll
        for (int r = 0; r < 2; r++) {
            int t  = tid + r * 256;
            int ml = t >> 2, kq = (t & 3) * 4;
            int m = bm + ml;
            float4 v = make_float4(0, 0, 0, 0);
            if (m < M) v = *reinterpret_cast<const float4*>(A + (size_t)m * 128 + k0 + kq);
            *reinterpret_cast<float4*>(As + ml * SROW + kq) = v;
        }
        {
            int nl = tid >> 2, kq = (tid & 3) * 4;
            float4 v = *reinterpret_cast<const float4*>(W + (size_t)(bn + nl) * 128 + k0 + kq);
            *reinterpret_cast<float4*>(Ws + nl * SROW + kq) = v;
        }
        __syncthreads();

        #pragma unroll
        for (int ks = 0; ks < 2; ks++) {
            int kb = ks * 8;
            unsigned ah[2][4], al[2][4], bh[4][2], bl[4][2];
            #pragma unroll
            for (int tm = 0; tm < 2; tm++) {
                int mb = wm * 32 + tm * 16;
                float f0 = As[(mb + g)     * SROW + kb + t4];
                float f1 = As[(mb + 8 + g) * SROW + kb + t4];
                float f2 = As[(mb + g)     * SROW + kb + t4 + 4];
                float f3 = As[(mb + 8 + g) * SROW + kb + t4 + 4];
                ah[tm][0] = cvt_tf32(f0); al[tm][0] = cvt_tf32(f0 - __uint_as_float(ah[tm][0]));
                ah[tm][1] = cvt_tf32(f1); al[tm][1] = cvt_tf32(f1 - __uint_as_float(ah[tm][1]));
                ah[tm][2] = cvt_tf32(f2); al[tm][2] = cvt_tf32(f2 - __uint_as_float(ah[tm][2]));
                ah[tm][3] = cvt_tf32(f3); al[tm][3] = cvt_tf32(f3 - __uint_as_float(ah[tm][3]));
            }
            #pragma unroll
            for (int tn = 0; tn < 4; tn++) {
                int nb = wn * 32 + tn * 8;
                float f0 = Ws[(nb + g) * SROW + kb + t4];
                float f1 = Ws[(nb + g) * SROW + kb + t4 + 4];
                bh[tn][0] = cvt_tf32(f0); bl[tn][0] = cvt_tf32(f0 - __uint_as_float(bh[tn][0]));
                bh[tn][1] = cvt_tf32(f1); bl[tn][1] = cvt_tf32(f1 - __uint_as_float(bh[tn][1]));
            }
            #pragma unroll
            for (int tm = 0; tm < 2; tm++)
                #pragma unroll
                for (int tn = 0; tn < 4; tn++) {
                    mma_tf32(acc[tm][tn], ah[tm], bh[tn]);
                    mma_tf32(acc[tm][tn], al[tm], bh[tn]);
                    mma_tf32(acc[tm][tn], ah[tm], bl[tn]);
                }
        }
        __syncthreads();
    }

    #pragma unroll
    for (int tm = 0; tm < 2; tm++) {
        #pragma unroll
        for (int tn = 0; tn < 4; tn++) {
            int row0 = bm + wm * 32 + tm * 16 + g;
            int col  = bn + wn * 32 + tn * 8 + t4 * 2;
            float b0 = __ldg(bias + col), b1 = __ldg(bias + col + 1);
            float v0 = acc[tm][tn][0] + b0;
            float v1 = acc[tm][tn][1] + b1;
            float v2 = acc[tm][tn][2] + b0;
            float v3 = acc[tm][tn][3] + b1;
            if (DO_SILU) {
                v0 = v0 / (1.0f + __expf(-v0));
                v1 = v1 / (1.0f + __expf(-v1));
                v2 = v2 / (1.0f + __expf(-v2));
                v3 = v3 / (1.0f + __expf(-v3));
            }
            if (OUT_HALF) {
                __half* outh = (__half*)outv;
                __half2 h01 = __floats2half2_rn(v0, v1);
                __half2 h23 = __floats2half2_rn(v2, v3);
                if (row0 < M)
                    *reinterpret_cast<__half2*>(outh + (size_t)row0 * N + col) = h01;
                if (row0 + 8 < M)
                    *reinterpret_cast<__half2*>(outh + (size_t)(row0 + 8) * N + col) = h23;
            } else {
                float* outf = (float*)outv;
                if (row0 < M)
                    *reinterpret_cast<float2*>(outf + (size_t)row0 * N + col) = make_float2(v0, v1);
                if (row0 + 8 < M)
                    *reinterpret_cast<float2*>(outf + (size_t)(row0 + 8) * N + col) = make_float2(v2, v3);
            }
        }
    }
}

// ---------------- aggregation: one warp per atom, fp16 gathers --------------
__global__ __launch_bounds__(128)
void k_agg(const float* __restrict__ q, const float* __restrict__ mu,
           const float* __restrict__ Wij, const float* __restrict__ dir,
           const int* __restrict__ idxj, float* __restrict__ out) {
    int warp = threadIdx.x >> 5;
    int lane = threadIdx.x & 31;
    int i = blockIdx.x * 4 + warp;
    if (i >= N_ATOMS) return;

    int s = g_offset[i], e = g_offset[i + 1];

    float4 aq = make_float4(0, 0, 0, 0);
    float4 a0 = aq, a1 = aq, a2 = aq;

    int t = s;
    int p_next = 0, j_next = 0;
    if (t < e) { p_next = g_pairidx[t]; j_next = idxj[p_next]; }

    for (; t < e; ++t) {
        int p = p_next, j = j_next;
        if (t + 1 < e) { p_next = g_pairidx[t + 1]; j_next = idxj[p_next]; }

        const float4* wp = reinterpret_cast<const float4*>(Wij) + (size_t)p * 96;
        const uint2*  xp = reinterpret_cast<const uint2*>(g_xh)  + (size_t)j * 96;
        const uint2*  mp = reinterpret_cast<const uint2*>(g_muh) + (size_t)j * 96;

        float4 w0 = wp[lane], w1 = wp[lane + 32], w2 = wp[lane + 64];
        uint2 xu0 = xp[lane], xu1 = xp[lane + 32], xu2 = xp[lane + 64];
        uint2 mu0 = mp[lane], mu1 = mp[lane + 32], mu2 = mp[lane + 64];

        float d0 = __ldg(dir + (size_t)p * 3 + 0);
        float d1 = __ldg(dir + (size_t)p * 3 + 1);
        float d2 = __ldg(dir + (size_t)p * 3 + 2);

        float4 x0 = h4tof4(xu0), x1 = h4tof4(xu1), x2 = h4tof4(xu2);
        float4 m0 = h4tof4(mu0), m1 = h4tof4(mu1), m2 = h4tof4(mu2);

        aq = f4fma(w0, x0, aq);                 // dq
        float4 R  = f4mul(w1, x1);              // dmuR
        float4 MM = f4mul(w2, x2);              // dmumu
        a0 = f4fma(MM, m0, f4fmas(R, d0, a0));
        a1 = f4fma(MM, m1, f4fmas(R, d1, a1));
        a2 = f4fma(MM, m2, f4fmas(R, d2, a2));
    }

    // outputs: q_out first [N,1,F], then mu_out [N,3,F] (fp32 originals added)
    const float4* qp = reinterpret_cast<const float4*>(q) + (size_t)i * 32;
    float4* oq = reinterpret_cast<float4*>(out) + (size_t)i * 32;
    oq[lane] = f4add(qp[lane], aq);

    const float4* mup = reinterpret_cast<const float4*>(mu) + (size_t)i * 96;
    float4* om = reinterpret_cast<float4*>(out + (size_t)N_ATOMS * FDIM) + (size_t)i * 96;
    om[lane]      = f4add(mup[lane],      a0);
    om[lane + 32] = f4add(mup[lane + 32], a1);
    om[lane + 64] = f4add(mup[lane + 64], a2);
}

// ---------------- launch ----------------------------------------------------
extern "C" void kernel_launch(void* const* d_in, const int* in_sizes, int n_in,
                              void* d_out, int out_size) {
    const float* q   = (const float*)d_in[0];
    const float* mu  = (const float*)d_in[1];
    const float* Wij = (const float*)d_in[2];
    const float* dir = (const float*)d_in[3];
    const int*   pl  = (const int*)d_in[4];
    const float* W1  = (const float*)d_in[5];
    const float* b1  = (const float*)d_in[6];
    const float* W2  = (const float*)d_in[7];
    const float* b2  = (const float*)d_in[8];
    float* out = (float*)d_out;

    const int* idx_i = pl;
    const int* idx_j = pl + N_PAIRS;

    float  *hbuf = nullptr;
    __half *xh   = nullptr;
    cudaGetSymbolAddress((void**)&hbuf, g_h);
    cudaGetSymbolAddress((void**)&xh,   g_xh);

    // CSR build (integer atomics only)
    k_zero   <<<(N_ATOMS + 255) / 256, 256>>>();
    k_hist   <<<(N_PAIRS + 255) / 256, 256>>>(idx_i);
    k_scan   <<<1, 1024>>>();
    k_scatter<<<(N_PAIRS + 255) / 256, 256>>>(idx_i);

    // mu -> fp16 mirror
    {
        size_t n4 = (size_t)N_ATOMS * F3 / 4;
        k_cvt_mu<<<(unsigned)((n4 + 255) / 256), 256>>>(mu);
    }

    // x = W2 . silu(W1 . q + b1) + b2   (3xTF32 TC GEMMs; x stored fp16)
    dim3 g1(FDIM / GBN, (N_ATOMS + GBM - 1) / GBM);
    gemm_tc<false, true><<<g1, 256>>>(q, W1, b1, hbuf, N_ATOMS, FDIM);
    dim3 g2(F3 / GBN, (N_ATOMS + GBM - 1) / GBM);
    gemm_tc<true, false><<<g2, 256>>>(hbuf, W2, b2, xh, N_ATOMS, F3);

    // per-atom gather + epilogue
    k_agg<<<N_ATOMS / 4, 128>>>(q, mu, Wij, dir, idx_j, out);
}

// round 5
// speedup vs baseline: 1.4469x; 1.1060x over previous
#include <cuda_runtime.h>
#include <cuda_fp16.h>

#define N_ATOMS 50000
#define N_PAIRS 800000
#define FDIM    128
#define F3      384

// ---------------- scratch (device globals; no runtime allocation) ----------
__device__ int    g_count [N_ATOMS];
__device__ int    g_cursor[N_ATOMS];
__device__ int    g_offset[N_ATOMS + 1];
__device__ int    g_pairidx[N_PAIRS];
__device__ float  g_h  [(size_t)N_ATOMS * FDIM];  // 25.6 MB
__device__ __half g_xh [(size_t)N_ATOMS * F3];    // 38.4 MB (x in fp16)
__device__ __half g_muh[(size_t)N_ATOMS * F3];    // 38.4 MB (mu in fp16)

// ---------------- small float4 helpers -------------------------------------
__device__ __forceinline__ float4 f4add(float4 a, float4 b) {
    return make_float4(a.x + b.x, a.y + b.y, a.z + b.z, a.w + b.w);
}
__device__ __forceinline__ float4 f4mul(float4 a, float4 b) {
    return make_float4(a.x * b.x, a.y * b.y, a.z * b.z, a.w * b.w);
}
__device__ __forceinline__ float4 f4fma(float4 a, float4 b, float4 c) {
    return make_float4(fmaf(a.x, b.x, c.x), fmaf(a.y, b.y, c.y),
                       fmaf(a.z, b.z, c.z), fmaf(a.w, b.w, c.w));
}
__device__ __forceinline__ float4 f4fmas(float4 a, float s, float4 c) {
    return make_float4(fmaf(a.x, s, c.x), fmaf(a.y, s, c.y),
                       fmaf(a.z, s, c.z), fmaf(a.w, s, c.w));
}
__device__ __forceinline__ float4 h4tof4(uint2 u) {
    __half2 a = *reinterpret_cast<__half2*>(&u.x);
    __half2 b = *reinterpret_cast<__half2*>(&u.y);
    float2 fa = __half22float2(a), fb = __half22float2(b);
    return make_float4(fa.x, fa.y, fb.x, fb.y);
}

// ---------------- CSR build -------------------------------------------------
__global__ void k_zero() {
    int i = blockIdx.x * blockDim.x + threadIdx.x;
    if (i < N_ATOMS) { g_count[i] = 0; g_cursor[i] = 0; }
}

__global__ void k_hist(const int* __restrict__ idx_i) {
    int p = blockIdx.x * blockDim.x + threadIdx.x;
    if (p < N_PAIRS) atomicAdd(&g_count[idx_i[p]], 1);
}

__global__ void k_scan() {
    __shared__ int warpsum[33];
    int lane = threadIdx.x & 31, wid = threadIdx.x >> 5;
    int running = 0;
    for (int base = 0; base < N_ATOMS; base += 1024) {
        int idx = base + (int)threadIdx.x;
        int v = (idx < N_ATOMS) ? g_count[idx] : 0;
        int incl = v;
        #pragma unroll
        for (int off = 1; off < 32; off <<= 1) {
            int t = __shfl_up_sync(0xffffffff, incl, off);
            if (lane >= off) incl += t;
        }
        if (lane == 31) warpsum[wid] = incl;
        __syncthreads();
        if (wid == 0) {
            int s = warpsum[lane];
            int si = s;
            #pragma unroll
            for (int off = 1; off < 32; off <<= 1) {
                int t = __shfl_up_sync(0xffffffff, si, off);
                if (lane >= off) si += t;
            }
            warpsum[lane] = si - s;
            if (lane == 31) warpsum[32] = si;
        }
        __syncthreads();
        if (idx < N_ATOMS) g_offset[idx] = running + warpsum[wid] + incl - v;
        running += warpsum[32];
        __syncthreads();
    }
    if (threadIdx.x == 0) g_offset[N_ATOMS] = running;
}

__global__ void k_scatter(const int* __restrict__ idx_i) {
    int p = blockIdx.x * blockDim.x + threadIdx.x;
    if (p < N_PAIRS) {
        int i = idx_i[p];
        int pos = atomicAdd(&g_cursor[i], 1);
        g_pairidx[g_offset[i] + pos] = p;
    }
}

// ---------------- mu -> fp16 mirror ----------------------------------------
__global__ void k_cvt_mu(const float* __restrict__ mu) {
    size_t i = (size_t)blockIdx.x * blockDim.x + threadIdx.x;
    size_t n4 = (size_t)N_ATOMS * F3 / 4;
    if (i >= n4) return;
    float4 v = reinterpret_cast<const float4*>(mu)[i];
    __half2 h0 = __floats2half2_rn(v.x, v.y);
    __half2 h1 = __floats2half2_rn(v.z, v.w);
    uint2 u;
    u.x = *reinterpret_cast<unsigned*>(&h0);
    u.y = *reinterpret_cast<unsigned*>(&h1);
    reinterpret_cast<uint2*>(g_muh)[i] = u;
}

// ---------------- 3xTF32 tensor-core GEMM ----------------------------------
__device__ __forceinline__ unsigned cvt_tf32(float x) {
    unsigned r; asm("cvt.rna.tf32.f32 %0, %1;" : "=r"(r) : "f"(x)); return r;
}
__device__ __forceinline__ void mma_tf32(float* d, const unsigned* a, const unsigned* b) {
    asm volatile(
        "mma.sync.aligned.m16n8k8.row.col.f32.tf32.tf32.f32 "
        "{%0,%1,%2,%3}, {%4,%5,%6,%7}, {%8,%9}, {%0,%1,%2,%3};"
        : "+f"(d[0]), "+f"(d[1]), "+f"(d[2]), "+f"(d[3])
        : "r"(a[0]), "r"(a[1]), "r"(a[2]), "r"(a[3]), "r"(b[0]), "r"(b[1]));
}

#define GBM 128
#define GBN 64
#define GBK 16
#define SROW 20

template<bool OUT_HALF, bool DO_SILU>
__global__ __launch_bounds__(256)
void gemm_tc(const float* __restrict__ A, const float* __restrict__ W,
             const float* __restrict__ bias, void* __restrict__ outv,
             int M, int N) {
    __shared__ float As[GBM * SROW];
    __shared__ float Ws[GBN * SROW];

    int tid  = threadIdx.x;
    int warp = tid >> 5, lane = tid & 31;
    int g = lane >> 2, t4 = lane & 3;
    int wm = warp >> 1, wn = warp & 1;
    int bm = blockIdx.y * GBM, bn = blockIdx.x * GBN;

    float acc[2][4][4];
    #pragma unroll
    for (int i = 0; i < 2; i++)
        #pragma unroll
        for (int j = 0; j < 4; j++)
            #pragma unroll
            for (int k = 0; k < 4; k++) acc[i][j][k] = 0.f;

    for (int k0 = 0; k0 < 128; k0 += GBK) {
        #pragma unroll
        for (int r = 0; r < 2; r++) {
            int t  = tid + r * 256;
            int ml = t >> 2, kq = (t & 3) * 4;
            int m = bm + ml;
            float4 v = make_float4(0, 0, 0, 0);
            if (m < M) v = *reinterpret_cast<const float4*>(A + (size_t)m * 128 + k0 + kq);
            *reinterpret_cast<float4*>(As + ml * SROW + kq) = v;
        }
        {
            int nl = tid >> 2, kq = (tid & 3) * 4;
            float4 v = *reinterpret_cast<const float4*>(W + (size_t)(bn + nl) * 128 + k0 + kq);
            *reinterpret_cast<float4*>(Ws + nl * SROW + kq) = v;
        }
        __syncthreads();

        #pragma unroll
        for (int ks = 0; ks < 2; ks++) {
            int kb = ks * 8;
            unsigned ah[2][4], al[2][4], bh[4][2], bl[4][2];
            #pragma unroll
            for (int tm = 0; tm < 2; tm++) {
                int mb = wm * 32 + tm * 16;
                float f0 = As[(mb + g)     * SROW + kb + t4];
                float f1 = As[(mb + 8 + g) * SROW + kb + t4];
                float f2 = As[(mb + g)     * SROW + kb + t4 + 4];
                float f3 = As[(mb + 8 + g) * SROW + kb + t4 + 4];
                ah[tm][0] = cvt_tf32(f0); al[tm][0] = cvt_tf32(f0 - __uint_as_float(ah[tm][0]));
                ah[tm][1] = cvt_tf32(f1); al[tm][1] = cvt_tf32(f1 - __uint_as_float(ah[tm][1]));
                ah[tm][2] = cvt_tf32(f2); al[tm][2] = cvt_tf32(f2 - __uint_as_float(ah[tm][2]));
                ah[tm][3] = cvt_tf32(f3); al[tm][3] = cvt_tf32(f3 - __uint_as_float(ah[tm][3]));
            }
            #pragma unroll
            for (int tn = 0; tn < 4; tn++) {
                int nb = wn * 32 + tn * 8;
                float f0 = Ws[(nb + g) * SROW + kb + t4];
                float f1 = Ws[(nb + g) * SROW + kb + t4 + 4];
                bh[tn][0] = cvt_tf32(f0); bl[tn][0] = cvt_tf32(f0 - __uint_as_float(bh[tn][0]));
                bh[tn][1] = cvt_tf32(f1); bl[tn][1] = cvt_tf32(f1 - __uint_as_float(bh[tn][1]));
            }
            #pragma unroll
            for (int tm = 0; tm < 2; tm++)
                #pragma unroll
                for (int tn = 0; tn < 4; tn++) {
                    mma_tf32(acc[tm][tn], ah[tm], bh[tn]);
                    mma_tf32(acc[tm][tn], al[tm], bh[tn]);
                    mma_tf32(acc[tm][tn], ah[tm], bl[tn]);
                }
        }
        __syncthreads();
    }

    #pragma unroll
    for (int tm = 0; tm < 2; tm++) {
        #pragma unroll
        for (int tn = 0; tn < 4; tn++) {
            int row0 = bm + wm * 32 + tm * 16 + g;
            int col  = bn + wn * 32 + tn * 8 + t4 * 2;
            float b0 = __ldg(bias + col), b1 = __ldg(bias + col + 1);
            float v0 = acc[tm][tn][0] + b0;
            float v1 = acc[tm][tn][1] + b1;
            float v2 = acc[tm][tn][2] + b0;
            float v3 = acc[tm][tn][3] + b1;
            if (DO_SILU) {
                v0 = v0 / (1.0f + __expf(-v0));
                v1 = v1 / (1.0f + __expf(-v1));
                v2 = v2 / (1.0f + __expf(-v2));
                v3 = v3 / (1.0f + __expf(-v3));
            }
            if (OUT_HALF) {
                __half* outh = (__half*)outv;
                __half2 h01 = __floats2half2_rn(v0, v1);
                __half2 h23 = __floats2half2_rn(v2, v3);
                if (row0 < M)
                    *reinterpret_cast<__half2*>(outh + (size_t)row0 * N + col) = h01;
                if (row0 + 8 < M)
                    *reinterpret_cast<__half2*>(outh + (size_t)(row0 + 8) * N + col) = h23;
            } else {
                float* outf = (float*)outv;
                if (row0 < M)
                    *reinterpret_cast<float2*>(outf + (size_t)row0 * N + col) = make_float2(v0, v1);
                if (row0 + 8 < M)
                    *reinterpret_cast<float2*>(outf + (size_t)(row0 + 8) * N + col) = make_float2(v2, v3);
            }
        }
    }
}

// ---------------- aggregation: one warp per atom, fp16 gathers --------------
__global__ __launch_bounds__(128)
void k_agg(const float* __restrict__ q, const float* __restrict__ mu,
           const float* __restrict__ Wij, const float* __restrict__ dir,
           const int* __restrict__ idxj, float* __restrict__ out) {
    int warp = threadIdx.x >> 5;
    int lane = threadIdx.x & 31;
    int i = blockIdx.x * 4 + warp;
    if (i >= N_ATOMS) return;

    int s = g_offset[i], e = g_offset[i + 1];

    float4 aq = make_float4(0, 0, 0, 0);
    float4 a0 = aq, a1 = aq, a2 = aq;

    // index prefetch depth 2 (breaks pairidx->idxj->data latency chain)
    int p0 = 0, j0 = 0, p1 = 0, j1 = 0;
    if (s < e)     { p0 = g_pairidx[s];     j0 = idxj[p0]; }
    if (s + 1 < e) { p1 = g_pairidx[s + 1]; j1 = idxj[p1]; }

    for (int t = s; t < e; ++t) {
        int p = p0, j = j0;
        p0 = p1; j0 = j1;
        if (t + 2 < e) { p1 = g_pairidx[t + 2]; j1 = idxj[p1]; }

        const float4* wp = reinterpret_cast<const float4*>(Wij) + (size_t)p * 96;
        const uint2*  xp = reinterpret_cast<const uint2*>(g_xh)  + (size_t)j * 96;
        const uint2*  mp = reinterpret_cast<const uint2*>(g_muh) + (size_t)j * 96;

        // Wij: read-once stream -> evict-first, keep L2 for x/mu working set
        float4 w0 = __ldcs(wp + lane);
        float4 w1 = __ldcs(wp + lane + 32);
        float4 w2 = __ldcs(wp + lane + 64);
        uint2 xu0 = xp[lane], xu1 = xp[lane + 32], xu2 = xp[lane + 64];
        uint2 mu0 = mp[lane], mu1 = mp[lane + 32], mu2 = mp[lane + 64];

        float d0 = __ldg(dir + (size_t)p * 3 + 0);
        float d1 = __ldg(dir + (size_t)p * 3 + 1);
        float d2 = __ldg(dir + (size_t)p * 3 + 2);

        float4 x0 = h4tof4(xu0), x1 = h4tof4(xu1), x2 = h4tof4(xu2);
        float4 m0 = h4tof4(mu0), m1 = h4tof4(mu1), m2 = h4tof4(mu2);

        aq = f4fma(w0, x0, aq);
        float4 R  = f4mul(w1, x1);
        float4 MM = f4mul(w2, x2);
        a0 = f4fma(MM, m0, f4fmas(R, d0, a0));
        a1 = f4fma(MM, m1, f4fmas(R, d1, a1));
        a2 = f4fma(MM, m2, f4fmas(R, d2, a2));
    }

    const float4* qp = reinterpret_cast<const float4*>(q) + (size_t)i * 32;
    float4* oq = reinterpret_cast<float4*>(out) + (size_t)i * 32;
    oq[lane] = f4add(qp[lane], aq);

    const float4* mup = reinterpret_cast<const float4*>(mu) + (size_t)i * 96;
    float4* om = reinterpret_cast<float4*>(out + (size_t)N_ATOMS * FDIM) + (size_t)i * 96;
    om[lane]      = f4add(mup[lane],      a0);
    om[lane + 32] = f4add(mup[lane + 32], a1);
    om[lane + 64] = f4add(mup[lane + 64], a2);
}

// ---------------- launch ----------------------------------------------------
static cudaStream_t s_side = nullptr;
static cudaEvent_t  s_evFork = nullptr, s_evJoin = nullptr;

extern "C" void kernel_launch(void* const* d_in, const int* in_sizes, int n_in,
                              void* d_out, int out_size) {
    const float* q   = (const float*)d_in[0];
    const float* mu  = (const float*)d_in[1];
    const float* Wij = (const float*)d_in[2];
    const float* dir = (const float*)d_in[3];
    const int*   pl  = (const int*)d_in[4];
    const float* W1  = (const float*)d_in[5];
    const float* b1  = (const float*)d_in[6];
    const float* W2  = (const float*)d_in[7];
    const float* b2  = (const float*)d_in[8];
    float* out = (float*)d_out;

    const int* idx_i = pl;
    const int* idx_j = pl + N_PAIRS;

    float  *hbuf = nullptr;
    __half *xh   = nullptr;
    cudaGetSymbolAddress((void**)&hbuf, g_h);
    cudaGetSymbolAddress((void**)&xh,   g_xh);

    // one-time host resource init (happens on the pre-capture correctness call;
    // device work per call is identical)
    if (!s_side) {
        cudaStreamCreateWithFlags(&s_side, cudaStreamNonBlocking);
        cudaEventCreateWithFlags(&s_evFork, cudaEventDisableTiming);
        cudaEventCreateWithFlags(&s_evJoin, cudaEventDisableTiming);
    }

    // fork: CSR chain on side stream, GEMM chain on main stream
    cudaEventRecord(s_evFork, 0);
    cudaStreamWaitEvent(s_side, s_evFork, 0);

    k_zero   <<<(N_ATOMS + 255) / 256, 256, 0, s_side>>>();
    k_hist   <<<(N_PAIRS + 255) / 256, 256, 0, s_side>>>(idx_i);
    k_scan   <<<1, 1024, 0, s_side>>>();
    k_scatter<<<(N_PAIRS + 255) / 256, 256, 0, s_side>>>(idx_i);
    cudaEventRecord(s_evJoin, s_side);

    {
        size_t n4 = (size_t)N_ATOMS * F3 / 4;
        k_cvt_mu<<<(unsigned)((n4 + 255) / 256), 256>>>(mu);
    }
    dim3 g1(FDIM / GBN, (N_ATOMS + GBM - 1) / GBM);
    gemm_tc<false, true><<<g1, 256>>>(q, W1, b1, hbuf, N_ATOMS, FDIM);
    dim3 g2(F3 / GBN, (N_ATOMS + GBM - 1) / GBM);
    gemm_tc<true, false><<<g2, 256>>>(hbuf, W2, b2, xh, N_ATOMS, F3);

    // join, then aggregate
    cudaStreamWaitEvent(0, s_evJoin, 0);
    k_agg<<<N_ATOMS / 4, 128>>>(q, mu, Wij, dir, idx_j, out);
}

// round 6
// speedup vs baseline: 1.5435x; 1.0668x over previous
#include <cuda_runtime.h>
#include <cuda_fp16.h>

#define N_ATOMS 50000
#define N_PAIRS 800000
#define FDIM    128
#define F3      384

// ---------------- scratch (device globals; no runtime allocation) ----------
__device__ int    g_count [N_ATOMS];
__device__ int    g_cursor[N_ATOMS];
__device__ int    g_offset[N_ATOMS + 1];
__device__ int    g_pairidx[N_PAIRS];
__device__ float  g_h  [(size_t)N_ATOMS * FDIM];  // 25.6 MB
__device__ __half g_xh [(size_t)N_ATOMS * F3];    // 38.4 MB (x in fp16)
__device__ __half g_muh[(size_t)N_ATOMS * F3];    // 38.4 MB (mu in fp16)

// ---------------- small float4 helpers -------------------------------------
__device__ __forceinline__ float4 f4add(float4 a, float4 b) {
    return make_float4(a.x + b.x, a.y + b.y, a.z + b.z, a.w + b.w);
}
__device__ __forceinline__ float4 f4mul(float4 a, float4 b) {
    return make_float4(a.x * b.x, a.y * b.y, a.z * b.z, a.w * b.w);
}
__device__ __forceinline__ float4 f4fma(float4 a, float4 b, float4 c) {
    return make_float4(fmaf(a.x, b.x, c.x), fmaf(a.y, b.y, c.y),
                       fmaf(a.z, b.z, c.z), fmaf(a.w, b.w, c.w));
}
__device__ __forceinline__ float4 f4fmas(float4 a, float s, float4 c) {
    return make_float4(fmaf(a.x, s, c.x), fmaf(a.y, s, c.y),
                       fmaf(a.z, s, c.z), fmaf(a.w, s, c.w));
}
__device__ __forceinline__ float4 h4tof4(uint2 u) {
    __half2 a = *reinterpret_cast<__half2*>(&u.x);
    __half2 b = *reinterpret_cast<__half2*>(&u.y);
    float2 fa = __half22float2(a), fb = __half22float2(b);
    return make_float4(fa.x, fa.y, fb.x, fb.y);
}

// ---------------- CSR build -------------------------------------------------
__global__ void k_zero() {
    int i = blockIdx.x * blockDim.x + threadIdx.x;
    if (i < N_ATOMS) { g_count[i] = 0; g_cursor[i] = 0; }
}

__global__ void k_hist(const int* __restrict__ idx_i) {
    int p = blockIdx.x * blockDim.x + threadIdx.x;
    if (p < N_PAIRS) atomicAdd(&g_count[idx_i[p]], 1);
}

__global__ void k_scan() {
    __shared__ int warpsum[33];
    int lane = threadIdx.x & 31, wid = threadIdx.x >> 5;
    int running = 0;
    for (int base = 0; base < N_ATOMS; base += 1024) {
        int idx = base + (int)threadIdx.x;
        int v = (idx < N_ATOMS) ? g_count[idx] : 0;
        int incl = v;
        #pragma unroll
        for (int off = 1; off < 32; off <<= 1) {
            int t = __shfl_up_sync(0xffffffff, incl, off);
            if (lane >= off) incl += t;
        }
        if (lane == 31) warpsum[wid] = incl;
        __syncthreads();
        if (wid == 0) {
            int s = warpsum[lane];
            int si = s;
            #pragma unroll
            for (int off = 1; off < 32; off <<= 1) {
                int t = __shfl_up_sync(0xffffffff, si, off);
                if (lane >= off) si += t;
            }
            warpsum[lane] = si - s;
            if (lane == 31) warpsum[32] = si;
        }
        __syncthreads();
        if (idx < N_ATOMS) g_offset[idx] = running + warpsum[wid] + incl - v;
        running += warpsum[32];
        __syncthreads();
    }
    if (threadIdx.x == 0) g_offset[N_ATOMS] = running;
}

__global__ void k_scatter(const int* __restrict__ idx_i) {
    int p = blockIdx.x * blockDim.x + threadIdx.x;
    if (p < N_PAIRS) {
        int i = idx_i[p];
        int pos = atomicAdd(&g_cursor[i], 1);
        g_pairidx[g_offset[i] + pos] = p;
    }
}

// ---------------- mu -> fp16 mirror ----------------------------------------
__global__ void k_cvt_mu(const float* __restrict__ mu) {
    size_t i = (size_t)blockIdx.x * blockDim.x + threadIdx.x;
    size_t n4 = (size_t)N_ATOMS * F3 / 4;
    if (i >= n4) return;
    float4 v = reinterpret_cast<const float4*>(mu)[i];
    __half2 h0 = __floats2half2_rn(v.x, v.y);
    __half2 h1 = __floats2half2_rn(v.z, v.w);
    uint2 u;
    u.x = *reinterpret_cast<unsigned*>(&h0);
    u.y = *reinterpret_cast<unsigned*>(&h1);
    reinterpret_cast<uint2*>(g_muh)[i] = u;
}

// ---------------- 3xTF32 tensor-core GEMM ----------------------------------
__device__ __forceinline__ unsigned cvt_tf32(float x) {
    unsigned r; asm("cvt.rna.tf32.f32 %0, %1;" : "=r"(r) : "f"(x)); return r;
}
__device__ __forceinline__ void mma_tf32(float* d, const unsigned* a, const unsigned* b) {
    asm volatile(
        "mma.sync.aligned.m16n8k8.row.col.f32.tf32.tf32.f32 "
        "{%0,%1,%2,%3}, {%4,%5,%6,%7}, {%8,%9}, {%0,%1,%2,%3};"
        : "+f"(d[0]), "+f"(d[1]), "+f"(d[2]), "+f"(d[3])
        : "r"(a[0]), "r"(a[1]), "r"(a[2]), "r"(a[3]), "r"(b[0]), "r"(b[1]));
}

#define GBM 128
#define GBN 64
#define GBK 16
#define SROW 20

template<bool OUT_HALF, bool DO_SILU>
__global__ __launch_bounds__(256)
void gemm_tc(const float* __restrict__ A, const float* __restrict__ W,
             const float* __restrict__ bias, void* __restrict__ outv,
             int M, int N) {
    __shared__ float As[GBM * SROW];
    __shared__ float Ws[GBN * SROW];

    int tid  = threadIdx.x;
    int warp = tid >> 5, lane = tid & 31;
    int g = lane >> 2, t4 = lane & 3;
    int wm = warp >> 1, wn = warp & 1;
    int bm = blockIdx.y * GBM, bn = blockIdx.x * GBN;

    float acc[2][4][4];
    #pragma unroll
    for (int i = 0; i < 2; i++)
        #pragma unroll
        for (int j = 0; j < 4; j++)
            #pragma unroll
            for (int k = 0; k < 4; k++) acc[i][j][k] = 0.f;

    for (int k0 = 0; k0 < 128; k0 += GBK) {
        #pragma unroll
        for (int r = 0; r < 2; r++) {
            int t  = tid + r * 256;
            int ml = t >> 2, kq = (t & 3) * 4;
            int m = bm + ml;
            float4 v = make_float4(0, 0, 0, 0);
            if (m < M) v = *reinterpret_cast<const float4*>(A + (size_t)m * 128 + k0 + kq);
            *reinterpret_cast<float4*>(As + ml * SROW + kq) = v;
        }
        {
            int nl = tid >> 2, kq = (tid & 3) * 4;
            float4 v = *reinterpret_cast<const float4*>(W + (size_t)(bn + nl) * 128 + k0 + kq);
            *reinterpret_cast<float4*>(Ws + nl * SROW + kq) = v;
        }
        __syncthreads();

        #pragma unroll
        for (int ks = 0; ks < 2; ks++) {
            int kb = ks * 8;
            unsigned ah[2][4], al[2][4], bh[4][2], bl[4][2];
            #pragma unroll
            for (int tm = 0; tm < 2; tm++) {
                int mb = wm * 32 + tm * 16;
                float f0 = As[(mb + g)     * SROW + kb + t4];
                float f1 = As[(mb + 8 + g) * SROW + kb + t4];
                float f2 = As[(mb + g)     * SROW + kb + t4 + 4];
                float f3 = As[(mb + 8 + g) * SROW + kb + t4 + 4];
                ah[tm][0] = cvt_tf32(f0); al[tm][0] = cvt_tf32(f0 - __uint_as_float(ah[tm][0]));
                ah[tm][1] = cvt_tf32(f1); al[tm][1] = cvt_tf32(f1 - __uint_as_float(ah[tm][1]));
                ah[tm][2] = cvt_tf32(f2); al[tm][2] = cvt_tf32(f2 - __uint_as_float(ah[tm][2]));
                ah[tm][3] = cvt_tf32(f3); al[tm][3] = cvt_tf32(f3 - __uint_as_float(ah[tm][3]));
            }
            #pragma unroll
            for (int tn = 0; tn < 4; tn++) {
                int nb = wn * 32 + tn * 8;
                float f0 = Ws[(nb + g) * SROW + kb + t4];
                float f1 = Ws[(nb + g) * SROW + kb + t4 + 4];
                bh[tn][0] = cvt_tf32(f0); bl[tn][0] = cvt_tf32(f0 - __uint_as_float(bh[tn][0]));
                bh[tn][1] = cvt_tf32(f1); bl[tn][1] = cvt_tf32(f1 - __uint_as_float(bh[tn][1]));
            }
            #pragma unroll
            for (int tm = 0; tm < 2; tm++)
                #pragma unroll
                for (int tn = 0; tn < 4; tn++) {
                    mma_tf32(acc[tm][tn], ah[tm], bh[tn]);
                    mma_tf32(acc[tm][tn], al[tm], bh[tn]);
                    mma_tf32(acc[tm][tn], ah[tm], bl[tn]);
                }
        }
        __syncthreads();
    }

    #pragma unroll
    for (int tm = 0; tm < 2; tm++) {
        #pragma unroll
        for (int tn = 0; tn < 4; tn++) {
            int row0 = bm + wm * 32 + tm * 16 + g;
            int col  = bn + wn * 32 + tn * 8 + t4 * 2;
            float b0 = __ldg(bias + col), b1 = __ldg(bias + col + 1);
            float v0 = acc[tm][tn][0] + b0;
            float v1 = acc[tm][tn][1] + b1;
            float v2 = acc[tm][tn][2] + b0;
            float v3 = acc[tm][tn][3] + b1;
            if (DO_SILU) {
                v0 = v0 / (1.0f + __expf(-v0));
                v1 = v1 / (1.0f + __expf(-v1));
                v2 = v2 / (1.0f + __expf(-v2));
                v3 = v3 / (1.0f + __expf(-v3));
            }
            if (OUT_HALF) {
                __half* outh = (__half*)outv;
                __half2 h01 = __floats2half2_rn(v0, v1);
                __half2 h23 = __floats2half2_rn(v2, v3);
                if (row0 < M)
                    *reinterpret_cast<__half2*>(outh + (size_t)row0 * N + col) = h01;
                if (row0 + 8 < M)
                    *reinterpret_cast<__half2*>(outh + (size_t)(row0 + 8) * N + col) = h23;
            } else {
                float* outf = (float*)outv;
                if (row0 < M)
                    *reinterpret_cast<float2*>(outf + (size_t)row0 * N + col) = make_float2(v0, v1);
                if (row0 + 8 < M)
                    *reinterpret_cast<float2*>(outf + (size_t)(row0 + 8) * N + col) = make_float2(v2, v3);
            }
        }
    }
}

// ---------------- aggregation: software-pipelined gathers -------------------
struct PairData {
    float4 w0, w1, w2;
    uint2  x0, x1, x2, m0, m1, m2;
    float  d0, d1, d2;
};

__device__ __forceinline__ void load_pair(PairData& D, int p, int j, int lane,
                                          const float* __restrict__ Wij,
                                          const float* __restrict__ dir) {
    const float4* wp = reinterpret_cast<const float4*>(Wij) + (size_t)p * 96;
    const uint2*  xp = reinterpret_cast<const uint2*>(g_xh)  + (size_t)j * 96;
    const uint2*  mp = reinterpret_cast<const uint2*>(g_muh) + (size_t)j * 96;
    D.w0 = __ldcs(wp + lane);
    D.w1 = __ldcs(wp + lane + 32);
    D.w2 = __ldcs(wp + lane + 64);
    D.x0 = xp[lane]; D.x1 = xp[lane + 32]; D.x2 = xp[lane + 64];
    D.m0 = mp[lane]; D.m1 = mp[lane + 32]; D.m2 = mp[lane + 64];
    D.d0 = __ldg(dir + (size_t)p * 3 + 0);
    D.d1 = __ldg(dir + (size_t)p * 3 + 1);
    D.d2 = __ldg(dir + (size_t)p * 3 + 2);
}

__device__ __forceinline__ void accum_pair(const PairData& D, float4& aq,
                                           float4& a0, float4& a1, float4& a2) {
    float4 x0 = h4tof4(D.x0), x1 = h4tof4(D.x1), x2 = h4tof4(D.x2);
    float4 m0 = h4tof4(D.m0), m1 = h4tof4(D.m1), m2 = h4tof4(D.m2);
    aq = f4fma(D.w0, x0, aq);
    float4 R  = f4mul(D.w1, x1);
    float4 MM = f4mul(D.w2, x2);
    a0 = f4fma(MM, m0, f4fmas(R, D.d0, a0));
    a1 = f4fma(MM, m1, f4fmas(R, D.d1, a1));
    a2 = f4fma(MM, m2, f4fmas(R, D.d2, a2));
}

__global__ __launch_bounds__(128)
void k_agg(const float* __restrict__ q, const float* __restrict__ mu,
           const float* __restrict__ Wij, const float* __restrict__ dir,
           const int* __restrict__ idxj, float* __restrict__ out) {
    int warp = threadIdx.x >> 5;
    int lane = threadIdx.x & 31;
    int i = blockIdx.x * 4 + warp;
    if (i >= N_ATOMS) return;

    int s = g_offset[i], e = g_offset[i + 1];

    float4 aq = make_float4(0, 0, 0, 0);
    float4 a0 = aq, a1 = aq, a2 = aq;

    // index stream: (pc,jc) = indices for next pair to LOAD; (pn,jn) one ahead
    int pc = 0, jc = 0, pn = 0, jn = 0;
    if (s < e)     { pc = __ldg(g_pairidx + s);     jc = __ldg(idxj + pc); }
    if (s + 1 < e) { pn = __ldg(g_pairidx + s + 1); jn = __ldg(idxj + pn); }

    PairData A, B;
    int t = s;
    if (t < e) {
        load_pair(A, pc, jc, lane, Wij, dir);
        // advance index stream; prefetch position s+2
        pc = pn; jc = jn;
        if (s + 2 < e) { pn = __ldg(g_pairidx + s + 2); jn = __ldg(idxj + pn); }
    }

    while (t < e) {
        if (t + 1 < e) {
            load_pair(B, pc, jc, lane, Wij, dir);
            pc = pn; jc = jn;
            if (t + 3 < e) { pn = __ldg(g_pairidx + t + 3); jn = __ldg(idxj + pn); }
        }
        accum_pair(A, aq, a0, a1, a2);
        ++t;
        if (t >= e) break;
        if (t + 1 < e) {
            load_pair(A, pc, jc, lane, Wij, dir);
            pc = pn; jc = jn;
            if (t + 3 < e) { pn = __ldg(g_pairidx + t + 3); jn = __ldg(idxj + pn); }
        }
        accum_pair(B, aq, a0, a1, a2);
        ++t;
    }

    const float4* qp = reinterpret_cast<const float4*>(q) + (size_t)i * 32;
    float4* oq = reinterpret_cast<float4*>(out) + (size_t)i * 32;
    oq[lane] = f4add(qp[lane], aq);

    const float4* mup = reinterpret_cast<const float4*>(mu) + (size_t)i * 96;
    float4* om = reinterpret_cast<float4*>(out + (size_t)N_ATOMS * FDIM) + (size_t)i * 96;
    om[lane]      = f4add(mup[lane],      a0);
    om[lane + 32] = f4add(mup[lane + 32], a1);
    om[lane + 64] = f4add(mup[lane + 64], a2);
}

// ---------------- launch ----------------------------------------------------
static cudaStream_t s_side = nullptr;
static cudaEvent_t  s_evFork = nullptr, s_evJoin = nullptr;

extern "C" void kernel_launch(void* const* d_in, const int* in_sizes, int n_in,
                              void* d_out, int out_size) {
    const float* q   = (const float*)d_in[0];
    const float* mu  = (const float*)d_in[1];
    const float* Wij = (const float*)d_in[2];
    const float* dir = (const float*)d_in[3];
    const int*   pl  = (const int*)d_in[4];
    const float* W1  = (const float*)d_in[5];
    const float* b1  = (const float*)d_in[6];
    const float* W2  = (const float*)d_in[7];
    const float* b2  = (const float*)d_in[8];
    float* out = (float*)d_out;

    const int* idx_i = pl;
    const int* idx_j = pl + N_PAIRS;

    float  *hbuf = nullptr;
    __half *xh   = nullptr;
    cudaGetSymbolAddress((void**)&hbuf, g_h);
    cudaGetSymbolAddress((void**)&xh,   g_xh);

    if (!s_side) {
        cudaStreamCreateWithFlags(&s_side, cudaStreamNonBlocking);
        cudaEventCreateWithFlags(&s_evFork, cudaEventDisableTiming);
        cudaEventCreateWithFlags(&s_evJoin, cudaEventDisableTiming);
    }

    // fork: CSR chain + mu conversion on side stream, GEMM chain on main
    cudaEventRecord(s_evFork, 0);
    cudaStreamWaitEvent(s_side, s_evFork, 0);

    k_zero   <<<(N_ATOMS + 255) / 256, 256, 0, s_side>>>();
    k_hist   <<<(N_PAIRS + 255) / 256, 256, 0, s_side>>>(idx_i);
    k_scan   <<<1, 1024, 0, s_side>>>();
    k_scatter<<<(N_PAIRS + 255) / 256, 256, 0, s_side>>>(idx_i);
    {
        size_t n4 = (size_t)N_ATOMS * F3 / 4;
        k_cvt_mu<<<(unsigned)((n4 + 255) / 256), 256, 0, s_side>>>(mu);
    }
    cudaEventRecord(s_evJoin, s_side);

    dim3 g1(FDIM / GBN, (N_ATOMS + GBM - 1) / GBM);
    gemm_tc<false, true><<<g1, 256>>>(q, W1, b1, hbuf, N_ATOMS, FDIM);
    dim3 g2(F3 / GBN, (N_ATOMS + GBM - 1) / GBM);
    gemm_tc<true, false><<<g2, 256>>>(hbuf, W2, b2, xh, N_ATOMS, F3);

    // join, then aggregate
    cudaStreamWaitEvent(0, s_evJoin, 0);
    k_agg<<<N_ATOMS / 4, 128>>>(q, mu, Wij, dir, idx_j, out);
}